// round 16
// baseline (speedup 1.0000x reference)
#include <cuda_runtime.h>
#include <cuda_bf16.h>
#include <math.h>
#include <stdint.h>

#define NN 50000
#define NE 800000
#define F 128
#define HEADS 4
#define HD 32
#define NG 64
#define TILES64 ((NN + 63) / 64)   // 782
#define HTILES 391                 // tiles per half
#define SPLIT (HTILES * 64)        // 25024 row/node split
#define SAS 136                    // smem row stride in bf16 elems (272B: bank-safe)
#define SMEMSZ ((2 * 64 + 2 * 128) * SAS * 2)   // 104448 bytes -> 2 CTAs/SM

// ---------------- static device scratch ----------------
__device__ __align__(16) float g_h[NN * F];
__device__ __align__(16) float g_xl[NN * F];
__device__ __align__(16) float g_xr[NN * F];
__device__ __align__(16) float g_pool[NG * F];
__device__ float g_cnt[NG];

__device__ int g_ei32[2 * NE];
__device__ int g_batch32[NN];
__device__ int g_is64;

// CSR by destination
__device__ int g_deg[NN];
__device__ int g_rowptr[NN + 1];
__device__ int g_cursor[NN];
__device__ int g_csrsrc[NE];

// 7 weight matrices bf16 hi/lo, transposed to [n][k] row-major:
// 0=emb, 1..3=lin_l, 4..6=lin_r
__device__ __align__(16) __nv_bfloat16 g_Whi[7 * 16384];
__device__ __align__(16) __nv_bfloat16 g_Wlo[7 * 16384];

// ---------------- dtype sniff ----------------
__global__ void sniff_dtype(const void* ei) {
    __shared__ int nz;
    if (threadIdx.x == 0) nz = 0;
    __syncthreads();
    const int* p = (const int*)ei;
    if (p[2 * threadIdx.x + 1] != 0) atomicOr(&nz, 1);
    __syncthreads();
    if (threadIdx.x == 0) g_is64 = (nz == 0) ? 1 : 0;
}

__global__ void convert_idx(const void* src, int* dst, int n) {
    int i = blockIdx.x * blockDim.x + threadIdx.x;
    if (i >= n) return;
    if (g_is64) dst[i] = (int)((const long long*)src)[i];
    else        dst[i] = ((const int*)src)[i];
}

// ---------------- CSR build ----------------
__global__ void csr_count_zero() {
    int i = blockIdx.x * blockDim.x + threadIdx.x;
    if (i < NN) g_deg[i] = 0;
}

__global__ void convert_count(const void* ei) {
    int e = blockIdx.x * blockDim.x + threadIdx.x;
    if (e >= NE) return;
    int s, d;
    if (g_is64) {
        s = (int)((const long long*)ei)[e];
        d = (int)((const long long*)ei)[NE + e];
    } else {
        s = ((const int*)ei)[e];
        d = ((const int*)ei)[NE + e];
    }
    g_ei32[e] = s;
    g_ei32[NE + e] = d;
    atomicAdd(&g_deg[d], 1);
}

__global__ void csr_scan() {
    __shared__ int wsum[32];
    __shared__ int carry_s;
    int tid = threadIdx.x, lane = tid & 31, wid = tid >> 5;
    if (tid == 0) carry_s = 0;
    __syncthreads();
    for (int base = 0; base < NN; base += 1024) {
        int i = base + tid;
        int v = (i < NN) ? g_deg[i] : 0;
        int x = v;
#pragma unroll
        for (int off = 1; off < 32; off <<= 1) {
            int y = __shfl_up_sync(0xffffffffu, x, off);
            if (lane >= off) x += y;
        }
        if (lane == 31) wsum[wid] = x;
        __syncthreads();
        if (wid == 0) {
            int y = wsum[lane];
#pragma unroll
            for (int off = 1; off < 32; off <<= 1) {
                int z = __shfl_up_sync(0xffffffffu, y, off);
                if (lane >= off) y += z;
            }
            wsum[lane] = y;
        }
        __syncthreads();
        int carry = carry_s;
        int excl = x - v + (wid > 0 ? wsum[wid - 1] : 0) + carry;
        if (i < NN) { g_rowptr[i] = excl; g_cursor[i] = excl; }
        int total = wsum[31];
        __syncthreads();
        if (tid == 0) carry_s = carry + total;
        __syncthreads();
    }
    if (threadIdx.x == 0) g_rowptr[NN] = carry_s;
}

__global__ void csr_fill() {
    int e = blockIdx.x * blockDim.x + threadIdx.x;
    if (e >= NE) return;
    int src = g_ei32[e];
    int dst = g_ei32[NE + e];
    int pos = atomicAdd(&g_cursor[dst], 1);
    g_csrsrc[pos] = src;
}

// ---------------- bf16 split of W (transposed to [n][k]) --------------------
__global__ void split_W_all(const float* __restrict__ emb_W,
                            const float* __restrict__ llW,
                            const float* __restrict__ lrW) {
    int idx = blockIdx.x * blockDim.x + threadIdx.x;
    if (idx >= 7 * 16384) return;
    int w = idx >> 14, e = idx & 16383;
    int nrow = e >> 7, k = e & 127;
    float v;
    if (w == 0)      v = emb_W[k * F + nrow];
    else if (w < 4)  v = llW[(size_t)(w - 1) * F * F + k * F + nrow];
    else             v = lrW[(size_t)(w - 4) * F * F + k * F + nrow];
    __nv_bfloat16 hi = __float2bfloat16_rn(v);
    __nv_bfloat16 lo = __float2bfloat16_rn(v - __bfloat162float(hi));
    g_Whi[idx] = hi;
    g_Wlo[idx] = lo;
}

// ---------------- HMMA GEMM machinery ----------------
__device__ __forceinline__ void ldm4(uint32_t* d, uint32_t addr) {
    asm volatile("ldmatrix.sync.aligned.m8n8.x4.shared.b16 {%0,%1,%2,%3}, [%4];"
                 : "=r"(d[0]), "=r"(d[1]), "=r"(d[2]), "=r"(d[3]) : "r"(addr));
}

__device__ __forceinline__ void mma16816(float* c, const uint32_t* a,
                                         uint32_t b0, uint32_t b1) {
    asm volatile(
        "mma.sync.aligned.m16n8k16.row.col.f32.bf16.bf16.f32 "
        "{%0,%1,%2,%3}, {%4,%5,%6,%7}, {%8,%9}, {%0,%1,%2,%3};"
        : "+f"(c[0]), "+f"(c[1]), "+f"(c[2]), "+f"(c[3])
        : "r"(a[0]), "r"(a[1]), "r"(a[2]), "r"(a[3]), "r"(b0), "r"(b1));
}

// shared GEMM body: stages A+B, runs mainloop, writes out (fp32 + bias)
__device__ __forceinline__ void gemm_body(
        const float* __restrict__ A,
        const __nv_bfloat16* __restrict__ Whi, const __nv_bfloat16* __restrict__ Wlo,
        const float* __restrict__ bias, float* __restrict__ out, int n,
        int row0, char* smem) {
    __nv_bfloat16* sAhi = (__nv_bfloat16*)smem;
    __nv_bfloat16* sAlo = sAhi + 64 * SAS;
    __nv_bfloat16* sBhi = sAlo + 64 * SAS;
    __nv_bfloat16* sBlo = sBhi + 128 * SAS;
    uint32_t uAhi = (uint32_t)__cvta_generic_to_shared(sAhi);
    uint32_t uAlo = (uint32_t)__cvta_generic_to_shared(sAlo);
    uint32_t uBhi = (uint32_t)__cvta_generic_to_shared(sBhi);
    uint32_t uBlo = (uint32_t)__cvta_generic_to_shared(sBlo);

    int tid = threadIdx.x, lane = tid & 31, wid = tid >> 5;

    for (int i = tid; i < 2048; i += 256) {
        int r = i >> 4, c = i & 15;
        *(uint4*)&sBhi[r * SAS + c * 8] = ((const uint4*)Whi)[i];
        *(uint4*)&sBlo[r * SAS + c * 8] = ((const uint4*)Wlo)[i];
    }
    for (int i = tid; i < 2048; i += 256) {
        int r = i >> 5, c4 = (i & 31) * 4;
        int gr = row0 + r;
        float4 v = make_float4(0.f, 0.f, 0.f, 0.f);
        if (gr < n) v = *(const float4*)&A[(size_t)gr * F + c4];
        __nv_bfloat162 h01 = __floats2bfloat162_rn(v.x, v.y);
        __nv_bfloat162 h23 = __floats2bfloat162_rn(v.z, v.w);
        __nv_bfloat162 l01 = __floats2bfloat162_rn(v.x - __bfloat162float(h01.x),
                                                   v.y - __bfloat162float(h01.y));
        __nv_bfloat162 l23 = __floats2bfloat162_rn(v.z - __bfloat162float(h23.x),
                                                   v.w - __bfloat162float(h23.y));
        *(__nv_bfloat162*)&sAhi[r * SAS + c4]     = h01;
        *(__nv_bfloat162*)&sAhi[r * SAS + c4 + 2] = h23;
        *(__nv_bfloat162*)&sAlo[r * SAS + c4]     = l01;
        *(__nv_bfloat162*)&sAlo[r * SAS + c4 + 2] = l23;
    }
    __syncthreads();

    int wm = wid & 1, wn = wid >> 1;
    int m_base = wm * 32, n_base = wn * 32;

    float c[2][4][4];
#pragma unroll
    for (int i = 0; i < 2; i++)
#pragma unroll
        for (int j = 0; j < 4; j++)
#pragma unroll
            for (int q = 0; q < 4; q++) c[i][j][q] = 0.f;

    int a_r = lane & 15, a_c8 = (lane >> 4) << 3;
    int b_r = (((lane >> 4) & 1) << 3) + (lane & 7), b_c8 = ((lane >> 3) & 1) << 3;

#pragma unroll
    for (int ks = 0; ks < 8; ks++) {
        int k0 = ks * 16;
        uint32_t ahi[2][4], alo[2][4];
#pragma unroll
        for (int i = 0; i < 2; i++) {
            uint32_t off = (uint32_t)((m_base + i * 16 + a_r) * SAS + k0 + a_c8) * 2;
            ldm4(ahi[i], uAhi + off);
            ldm4(alo[i], uAlo + off);
        }
#pragma unroll
        for (int jp = 0; jp < 2; jp++) {
            uint32_t off = (uint32_t)((n_base + jp * 16 + b_r) * SAS + k0 + b_c8) * 2;
            uint32_t bh[4], bl[4];
            ldm4(bh, uBhi + off);
            ldm4(bl, uBlo + off);
#pragma unroll
            for (int i = 0; i < 2; i++) {
                mma16816(c[i][2 * jp],     ahi[i], bh[0], bh[1]);
                mma16816(c[i][2 * jp],     alo[i], bh[0], bh[1]);
                mma16816(c[i][2 * jp],     ahi[i], bl[0], bl[1]);
                mma16816(c[i][2 * jp + 1], ahi[i], bh[2], bh[3]);
                mma16816(c[i][2 * jp + 1], alo[i], bh[2], bh[3]);
                mma16816(c[i][2 * jp + 1], ahi[i], bl[2], bl[3]);
            }
        }
    }

    int qr = lane >> 2, qc = (lane & 3) * 2;
#pragma unroll
    for (int i = 0; i < 2; i++) {
#pragma unroll
        for (int j = 0; j < 4; j++) {
            int r0g = row0 + m_base + i * 16 + qr;
            int nn0 = n_base + j * 8 + qc;
            float2 bb = __ldg((const float2*)&bias[nn0]);
            if (r0g < n) {
                float2 o = make_float2(c[i][j][0] + bb.x, c[i][j][1] + bb.y);
                *(float2*)&out[(size_t)r0g * F + nn0] = o;
            }
            if (r0g + 8 < n) {
                float2 o = make_float2(c[i][j][2] + bb.x, c[i][j][3] + bb.y);
                *(float2*)&out[(size_t)(r0g + 8) * F + nn0] = o;
            }
        }
    }
}

// single GEMM (embedding, full range)
__global__ void __launch_bounds__(256, 2) hmma_gemm(
        const float* __restrict__ A,
        const __nv_bfloat16* __restrict__ Whi, const __nv_bfloat16* __restrict__ Wlo,
        const float* __restrict__ bias, float* __restrict__ out, int n) {
    extern __shared__ __align__(16) char smem[];
    gemm_body(A, Whi, Wlo, bias, out, n, blockIdx.x * 64, smem);
}

// dual GEMM over a tile range: blockIdx.y selects (Wl->xl) or (Wr->xr)
__global__ void __launch_bounds__(256, 2) hmma_gemm_dual(
        const float* __restrict__ A,
        const __nv_bfloat16* __restrict__ Whi_l, const __nv_bfloat16* __restrict__ Wlo_l,
        const float* __restrict__ bias_l, float* __restrict__ out_l,
        const __nv_bfloat16* __restrict__ Whi_r, const __nv_bfloat16* __restrict__ Wlo_r,
        const float* __restrict__ bias_r, float* __restrict__ out_r,
        int n, int tile_base) {
    extern __shared__ __align__(16) char smem[];
    int row0 = (tile_base + blockIdx.x) * 64;
    if (blockIdx.y == 0)
        gemm_body(A, Whi_l, Wlo_l, bias_l, out_l, n, row0, smem);
    else
        gemm_body(A, Whi_r, Wlo_r, bias_r, out_r, n, row0, smem);
}

// ---------------- fused gather: softmax-attention aggregate + epilogue --------
__device__ __forceinline__ float lrelu(float v) {
    return (v > 0.f) ? v : 0.2f * v;
}

__device__ __forceinline__ float edge_partial(const float4& xl4, const float4& xr4,
                                              const float4& attv) {
    return lrelu(xl4.x + xr4.x) * attv.x
         + lrelu(xl4.y + xr4.y) * attv.y
         + lrelu(xl4.z + xr4.z) * attv.z
         + lrelu(xl4.w + xr4.w) * attv.w;
}

__global__ void __launch_bounds__(256) gat_gather(
        const float* __restrict__ att, const float* __restrict__ conv_b,
        const float* __restrict__ ln_g, const float* __restrict__ ln_b,
        int node_beg, int node_end) {
    int node = node_beg + ((blockIdx.x * blockDim.x + threadIdx.x) >> 5);
    int lane = threadIdx.x & 31;
    if (node >= node_end) return;
    int beg = g_rowptr[node];
    int end = g_rowptr[node + 1];

    float4 xr4 = *(const float4*)&g_xr[(size_t)node * F + lane * 4];
    float4 attv = __ldg((const float4*)&att[lane * 4]);

    float d = 0.f;
    float4 s = make_float4(0.f, 0.f, 0.f, 0.f);

    int e = beg;
    for (; e + 4 <= end; e += 4) {
        int si[4];
#pragma unroll
        for (int u = 0; u < 4; u++) si[u] = g_csrsrc[e + u];
        float4 a[4];
#pragma unroll
        for (int u = 0; u < 4; u++)
            a[u] = __ldg((const float4*)&g_xl[(size_t)si[u] * F + lane * 4]);

        float p[4];
#pragma unroll
        for (int u = 0; u < 4; u++) p[u] = edge_partial(a[u], xr4, attv);

#pragma unroll
        for (int off = 1; off <= 4; off <<= 1) {
#pragma unroll
            for (int u = 0; u < 4; u++)
                p[u] += __shfl_xor_sync(0xffffffffu, p[u], off);
        }

#pragma unroll
        for (int u = 0; u < 4; u++) {
            float w = __expf(p[u]);
            d += w;
            s.x += w * a[u].x;
            s.y += w * a[u].y;
            s.z += w * a[u].z;
            s.w += w * a[u].w;
        }
    }
    for (; e < end; e++) {
        int s0 = g_csrsrc[e];
        float4 a0 = __ldg((const float4*)&g_xl[(size_t)s0 * F + lane * 4]);
        float p = edge_partial(a0, xr4, attv);
        p += __shfl_xor_sync(0xffffffffu, p, 1);
        p += __shfl_xor_sync(0xffffffffu, p, 2);
        p += __shfl_xor_sync(0xffffffffu, p, 4);
        float w = __expf(p);
        d += w;
        s.x += w * a0.x;
        s.y += w * a0.y;
        s.z += w * a0.z;
        s.w += w * a0.w;
    }

    float invd = 1.0f / (d + 1e-16f);
    float4 cb = __ldg((const float4*)&conv_b[lane * 4]);
    float4 o;
    o.x = s.x * invd + cb.x;
    o.y = s.y * invd + cb.y;
    o.z = s.z * invd + cb.z;
    o.w = s.w * invd + cb.w;
    o.x = (o.x > 0.f) ? o.x : (__expf(o.x) - 1.f);
    o.y = (o.y > 0.f) ? o.y : (__expf(o.y) - 1.f);
    o.z = (o.z > 0.f) ? o.z : (__expf(o.z) - 1.f);
    o.w = (o.w > 0.f) ? o.w : (__expf(o.w) - 1.f);
    float4 res = *(const float4*)&g_h[(size_t)node * F + lane * 4];
    o.x += res.x; o.y += res.y; o.z += res.z; o.w += res.w;

    float sum = o.x + o.y + o.z + o.w;
#pragma unroll
    for (int off = 16; off; off >>= 1) sum += __shfl_xor_sync(0xffffffffu, sum, off);
    float mu = sum * (1.f / 128.f);
    float dx0 = o.x - mu, dx1 = o.y - mu, dx2 = o.z - mu, dx3 = o.w - mu;
    float sq = dx0 * dx0 + dx1 * dx1 + dx2 * dx2 + dx3 * dx3;
#pragma unroll
    for (int off = 16; off; off >>= 1) sq += __shfl_xor_sync(0xffffffffu, sq, off);
    float rstd = rsqrtf(sq * (1.f / 128.f) + 1e-5f);

    float4 lg = __ldg((const float4*)&ln_g[lane * 4]);
    float4 lb = __ldg((const float4*)&ln_b[lane * 4]);
    float4 w;
    w.x = dx0 * rstd * lg.x + lb.x;
    w.y = dx1 * rstd * lg.y + lb.y;
    w.z = dx2 * rstd * lg.z + lb.z;
    w.w = dx3 * rstd * lg.w + lb.w;
    *(float4*)&g_h[(size_t)node * F + lane * 4] = w;
}

// ---------------- pooling ----------------
__global__ void pool_zero() {
    int i = blockIdx.x * blockDim.x + threadIdx.x;
    if (i < NG * F) g_pool[i] = 0.f;
    if (i < NG) g_cnt[i] = 0.f;
}

__global__ void pool_accum(int node_beg, int node_end) {
    int node = node_beg + ((blockIdx.x * blockDim.x + threadIdx.x) >> 5);
    int lane = threadIdx.x & 31;
    if (node >= node_end) return;
    int g = g_batch32[node];
#pragma unroll
    for (int h = 0; h < HEADS; h++)
        atomicAdd(&g_pool[g * F + h * HD + lane],
                  g_h[(size_t)node * F + h * HD + lane]);
    if (lane == 0) atomicAdd(&g_cnt[g], 1.0f);
}

__global__ void pool_final(float* __restrict__ out) {
    int i = blockIdx.x * blockDim.x + threadIdx.x;
    if (i >= NG * F) return;
    out[i] = g_pool[i] / fmaxf(g_cnt[i >> 7], 1.0f);
}

// ---------------- launch ----------------
extern "C" void kernel_launch(void* const* d_in, const int* in_sizes, int n_in,
                              void* d_out, int out_size) {
    const float* x        = (const float*)d_in[0];
    const void*  ei_raw   = d_in[1];
    const void*  batch_raw= d_in[2];
    const float* emb_W    = (const float*)d_in[3];
    const float* emb_b    = (const float*)d_in[4];
    const float* lin_l_W  = (const float*)d_in[5];
    const float* lin_l_b  = (const float*)d_in[6];
    const float* lin_r_W  = (const float*)d_in[7];
    const float* lin_r_b  = (const float*)d_in[8];
    const float* att      = (const float*)d_in[9];
    const float* conv_b   = (const float*)d_in[10];
    const float* ln_g     = (const float*)d_in[11];
    const float* ln_b     = (const float*)d_in[12];
    float* out = (float*)d_out;

    float *p_h, *p_xl, *p_xr;
    int *p_batch;
    __nv_bfloat16 *p_Whi, *p_Wlo;
    cudaGetSymbolAddress((void**)&p_h, g_h);
    cudaGetSymbolAddress((void**)&p_xl, g_xl);
    cudaGetSymbolAddress((void**)&p_xr, g_xr);
    cudaGetSymbolAddress((void**)&p_batch, g_batch32);
    cudaGetSymbolAddress((void**)&p_Whi, g_Whi);
    cudaGetSymbolAddress((void**)&p_Wlo, g_Wlo);

    cudaFuncSetAttribute(hmma_gemm, cudaFuncAttributeMaxDynamicSharedMemorySize, SMEMSZ);
    cudaFuncSetAttribute(hmma_gemm_dual, cudaFuncAttributeMaxDynamicSharedMemorySize, SMEMSZ);

    // one-time side stream + events (host-side resources; no device memory)
    static cudaStream_t s2 = nullptr;
    static cudaEvent_t evSide = nullptr, evEmb = nullptr, evG1 = nullptr,
                       evG2 = nullptr, evH1 = nullptr, evH2 = nullptr;
    if (!s2) {
        cudaStreamCreateWithFlags(&s2, cudaStreamNonBlocking);
        cudaEventCreateWithFlags(&evSide, cudaEventDisableTiming);
        cudaEventCreateWithFlags(&evEmb, cudaEventDisableTiming);
        cudaEventCreateWithFlags(&evG1, cudaEventDisableTiming);
        cudaEventCreateWithFlags(&evG2, cudaEventDisableTiming);
        cudaEventCreateWithFlags(&evH1, cudaEventDisableTiming);
        cudaEventCreateWithFlags(&evH2, cudaEventDisableTiming);
    }

    const int ET_GRID = (NE + 255) / 256;
    const int H1_GRID = (SPLIT + 7) / 8;            // nodes [0, SPLIT)
    const int H2_GRID = ((NN - SPLIT) + 7) / 8;     // nodes [SPLIT, NN)

    // fork immediately: side stream does sniff + CSR build; main does weights
    cudaEventRecord(evG1, 0);
    cudaStreamWaitEvent(s2, evG1, 0);

    // side branch (s2): sniff + CSR build + batch convert + pool zero
    sniff_dtype<<<1, 1024, 0, s2>>>(ei_raw);
    csr_count_zero<<<(NN + 255) / 256, 256, 0, s2>>>();
    pool_zero<<<(NG * F + 255) / 256, 256, 0, s2>>>();
    convert_count<<<ET_GRID, 256, 0, s2>>>(ei_raw);
    convert_idx<<<(NN + 255) / 256, 256, 0, s2>>>(batch_raw, p_batch, NN);
    csr_scan<<<1, 1024, 0, s2>>>();
    csr_fill<<<ET_GRID, 256, 0, s2>>>();
    cudaEventRecord(evSide, s2);

    // main branch: weight split + embedding GEMM (full range)
    split_W_all<<<(7 * 16384 + 255) / 256, 256>>>(emb_W, lin_l_W, lin_r_W);
    hmma_gemm<<<TILES64, 256, SMEMSZ>>>(x, p_Whi, p_Wlo, emb_b, p_h, NN);
    cudaEventRecord(evEmb, 0);

    for (int l = 0; l < 3; l++) {
        const __nv_bfloat16* Whl = p_Whi + (size_t)(1 + l) * 16384;
        const __nv_bfloat16* Wll = p_Wlo + (size_t)(1 + l) * 16384;
        const __nv_bfloat16* Whr = p_Whi + (size_t)(4 + l) * 16384;
        const __nv_bfloat16* Wlr = p_Wlo + (size_t)(4 + l) * 16384;
        const float* bl = lin_l_b + (size_t)l * F;
        const float* br = lin_r_b + (size_t)l * F;

        // G1 on main: GEMM tiles [0, HTILES)  (needs H1_{l-1} — same stream; l==0: emb)
        hmma_gemm_dual<<<dim3(HTILES, 2), 256, SMEMSZ>>>(
            p_h, Whl, Wll, bl, p_xl, Whr, Wlr, br, p_xr, NN, 0);
        cudaEventRecord(evG1, 0);

        // G2 on s2: GEMM tiles [HTILES, TILES64)
        if (l == 0) cudaStreamWaitEvent(s2, evEmb, 0);   // needs emb g_h (s2 has H2_{l-1} otherwise)
        hmma_gemm_dual<<<dim3(TILES64 - HTILES, 2), 256, SMEMSZ, s2>>>(
            p_h, Whl, Wll, bl, p_xl, Whr, Wlr, br, p_xr, NN, HTILES);
        cudaEventRecord(evG2, s2);

        // H1 on main: needs G1 (stream) + G2 (event) + CSR (l==0)
        cudaStreamWaitEvent(0, evG2, 0);
        if (l == 0) cudaStreamWaitEvent(0, evSide, 0);
        gat_gather<<<H1_GRID, 256>>>(att + (size_t)l * F, conv_b + (size_t)l * F,
                                     ln_g + (size_t)l * F, ln_b + (size_t)l * F,
                                     0, SPLIT);
        cudaEventRecord(evH1, 0);

        // H2 on s2: needs G2 (stream) + G1 (event) [+ CSR via evG2-ordering? no:
        // CSR is on s2 itself, so s2 is already ordered after csr_fill]
        cudaStreamWaitEvent(s2, evG1, 0);
        gat_gather<<<H2_GRID, 256, 0, s2>>>(att + (size_t)l * F, conv_b + (size_t)l * F,
                                            ln_g + (size_t)l * F, ln_b + (size_t)l * F,
                                            SPLIT, NN);
        cudaEventRecord(evH2, s2);
        // next iteration: G1_{l+1} on main follows H1_l (stream order) and
        // overlaps H2_l on s2; G2_{l+1} on s2 follows H2_l (stream order).
    }

    // pool: P1 follows H1_last on main (overlaps H2_last), P2 waits evH2
    pool_accum<<<H1_GRID, 256>>>(0, SPLIT);
    cudaStreamWaitEvent(0, evH2, 0);
    pool_accum<<<H2_GRID, 256>>>(SPLIT, NN);
    pool_final<<<(NG * F + 255) / 256, 256>>>(out);
}

// round 17
// speedup vs baseline: 1.0149x; 1.0149x over previous
#include <cuda_runtime.h>
#include <cuda_bf16.h>
#include <math.h>
#include <stdint.h>

#define NN 50000
#define NE 800000
#define F 128
#define HEADS 4
#define HD 32
#define NG 64
#define TILES64 ((NN + 63) / 64)   // 782
#define SAS 136                    // smem row stride in bf16 elems (272B: bank-safe)
#define SMEMSZ ((2 * 64 + 2 * 128) * SAS * 2)   // 104448 bytes -> 2 CTAs/SM

// ---------------- static device scratch ----------------
__device__ __align__(16) float g_h[NN * F];
__device__ __align__(16) float g_xl[NN * F];
__device__ __align__(16) float g_xr[NN * F];
__device__ __align__(16) float g_pool[NG * F];
__device__ float g_cnt[NG];

__device__ int g_ei32[2 * NE];
__device__ int g_batch32[NN];
__device__ int g_is64;

// CSR by destination
__device__ int g_deg[NN];
__device__ int g_rowptr[NN + 1];
__device__ int g_cursor[NN];
__device__ int g_csrsrc[NE];

// 7 weight matrices bf16 hi/lo, transposed to [n][k] row-major:
// 0=emb, 1..3=lin_l, 4..6=lin_r
__device__ __align__(16) __nv_bfloat16 g_Whi[7 * 16384];
__device__ __align__(16) __nv_bfloat16 g_Wlo[7 * 16384];

// ---------------- dtype sniff ----------------
__global__ void sniff_dtype(const void* ei) {
    __shared__ int nz;
    if (threadIdx.x == 0) nz = 0;
    __syncthreads();
    const int* p = (const int*)ei;
    if (p[2 * threadIdx.x + 1] != 0) atomicOr(&nz, 1);
    __syncthreads();
    if (threadIdx.x == 0) g_is64 = (nz == 0) ? 1 : 0;
}

__global__ void convert_idx(const void* src, int* dst, int n) {
    int i = blockIdx.x * blockDim.x + threadIdx.x;
    if (i >= n) return;
    if (g_is64) dst[i] = (int)((const long long*)src)[i];
    else        dst[i] = ((const int*)src)[i];
}

// ---------------- CSR build ----------------
__global__ void csr_count_zero() {
    int i = blockIdx.x * blockDim.x + threadIdx.x;
    if (i < NN) g_deg[i] = 0;
}

__global__ void convert_count(const void* ei) {
    int e = blockIdx.x * blockDim.x + threadIdx.x;
    if (e >= NE) return;
    int s, d;
    if (g_is64) {
        s = (int)((const long long*)ei)[e];
        d = (int)((const long long*)ei)[NE + e];
    } else {
        s = ((const int*)ei)[e];
        d = ((const int*)ei)[NE + e];
    }
    g_ei32[e] = s;
    g_ei32[NE + e] = d;
    atomicAdd(&g_deg[d], 1);
}

__global__ void csr_scan() {
    __shared__ int wsum[32];
    __shared__ int carry_s;
    int tid = threadIdx.x, lane = tid & 31, wid = tid >> 5;
    if (tid == 0) carry_s = 0;
    __syncthreads();
    for (int base = 0; base < NN; base += 1024) {
        int i = base + tid;
        int v = (i < NN) ? g_deg[i] : 0;
        int x = v;
#pragma unroll
        for (int off = 1; off < 32; off <<= 1) {
            int y = __shfl_up_sync(0xffffffffu, x, off);
            if (lane >= off) x += y;
        }
        if (lane == 31) wsum[wid] = x;
        __syncthreads();
        if (wid == 0) {
            int y = wsum[lane];
#pragma unroll
            for (int off = 1; off < 32; off <<= 1) {
                int z = __shfl_up_sync(0xffffffffu, y, off);
                if (lane >= off) y += z;
            }
            wsum[lane] = y;
        }
        __syncthreads();
        int carry = carry_s;
        int excl = x - v + (wid > 0 ? wsum[wid - 1] : 0) + carry;
        if (i < NN) { g_rowptr[i] = excl; g_cursor[i] = excl; }
        int total = wsum[31];
        __syncthreads();
        if (tid == 0) carry_s = carry + total;
        __syncthreads();
    }
    if (threadIdx.x == 0) g_rowptr[NN] = carry_s;
}

__global__ void csr_fill() {
    int e = blockIdx.x * blockDim.x + threadIdx.x;
    if (e >= NE) return;
    int src = g_ei32[e];
    int dst = g_ei32[NE + e];
    int pos = atomicAdd(&g_cursor[dst], 1);
    g_csrsrc[pos] = src;
}

// ---------------- bf16 split of W (transposed to [n][k]) --------------------
// emb only (w = 0): unblocks the embedding GEMM immediately
__global__ void split_W_emb(const float* __restrict__ emb_W) {
    int e = blockIdx.x * blockDim.x + threadIdx.x;
    if (e >= 16384) return;
    int nrow = e >> 7, k = e & 127;
    float v = emb_W[k * F + nrow];
    __nv_bfloat16 hi = __float2bfloat16_rn(v);
    __nv_bfloat16 lo = __float2bfloat16_rn(v - __bfloat162float(hi));
    g_Whi[e] = hi;
    g_Wlo[e] = lo;
}

// layer matrices (w = 1..6): runs on a side stream under the emb GEMM
__global__ void split_W_rest(const float* __restrict__ llW,
                             const float* __restrict__ lrW) {
    int idx = blockIdx.x * blockDim.x + threadIdx.x;
    if (idx >= 6 * 16384) return;
    int w = 1 + (idx >> 14), e = idx & 16383;
    int nrow = e >> 7, k = e & 127;
    float v;
    if (w < 4) v = llW[(size_t)(w - 1) * F * F + k * F + nrow];
    else       v = lrW[(size_t)(w - 4) * F * F + k * F + nrow];
    g_Whi[(size_t)w * 16384 + e] = __float2bfloat16_rn(v);
    float hi = __bfloat162float(__float2bfloat16_rn(v));
    g_Wlo[(size_t)w * 16384 + e] = __float2bfloat16_rn(v - hi);
}

// ---------------- HMMA GEMM machinery ----------------
__device__ __forceinline__ void ldm4(uint32_t* d, uint32_t addr) {
    asm volatile("ldmatrix.sync.aligned.m8n8.x4.shared.b16 {%0,%1,%2,%3}, [%4];"
                 : "=r"(d[0]), "=r"(d[1]), "=r"(d[2]), "=r"(d[3]) : "r"(addr));
}

__device__ __forceinline__ void mma16816(float* c, const uint32_t* a,
                                         uint32_t b0, uint32_t b1) {
    asm volatile(
        "mma.sync.aligned.m16n8k16.row.col.f32.bf16.bf16.f32 "
        "{%0,%1,%2,%3}, {%4,%5,%6,%7}, {%8,%9}, {%0,%1,%2,%3};"
        : "+f"(c[0]), "+f"(c[1]), "+f"(c[2]), "+f"(c[3])
        : "r"(a[0]), "r"(a[1]), "r"(a[2]), "r"(a[3]), "r"(b0), "r"(b1));
}

// shared GEMM body: stages A+B, runs mainloop, writes out (fp32 + bias)
__device__ __forceinline__ void gemm_body(
        const float* __restrict__ A,
        const __nv_bfloat16* __restrict__ Whi, const __nv_bfloat16* __restrict__ Wlo,
        const float* __restrict__ bias, float* __restrict__ out, int n,
        char* smem) {
    __nv_bfloat16* sAhi = (__nv_bfloat16*)smem;
    __nv_bfloat16* sAlo = sAhi + 64 * SAS;
    __nv_bfloat16* sBhi = sAlo + 64 * SAS;
    __nv_bfloat16* sBlo = sBhi + 128 * SAS;
    uint32_t uAhi = (uint32_t)__cvta_generic_to_shared(sAhi);
    uint32_t uAlo = (uint32_t)__cvta_generic_to_shared(sAlo);
    uint32_t uBhi = (uint32_t)__cvta_generic_to_shared(sBhi);
    uint32_t uBlo = (uint32_t)__cvta_generic_to_shared(sBlo);

    int tid = threadIdx.x, lane = tid & 31, wid = tid >> 5;
    int row0 = blockIdx.x * 64;

    for (int i = tid; i < 2048; i += 256) {
        int r = i >> 4, c = i & 15;
        *(uint4*)&sBhi[r * SAS + c * 8] = ((const uint4*)Whi)[i];
        *(uint4*)&sBlo[r * SAS + c * 8] = ((const uint4*)Wlo)[i];
    }
    for (int i = tid; i < 2048; i += 256) {
        int r = i >> 5, c4 = (i & 31) * 4;
        int gr = row0 + r;
        float4 v = make_float4(0.f, 0.f, 0.f, 0.f);
        if (gr < n) v = *(const float4*)&A[(size_t)gr * F + c4];
        __nv_bfloat162 h01 = __floats2bfloat162_rn(v.x, v.y);
        __nv_bfloat162 h23 = __floats2bfloat162_rn(v.z, v.w);
        __nv_bfloat162 l01 = __floats2bfloat162_rn(v.x - __bfloat162float(h01.x),
                                                   v.y - __bfloat162float(h01.y));
        __nv_bfloat162 l23 = __floats2bfloat162_rn(v.z - __bfloat162float(h23.x),
                                                   v.w - __bfloat162float(h23.y));
        *(__nv_bfloat162*)&sAhi[r * SAS + c4]     = h01;
        *(__nv_bfloat162*)&sAhi[r * SAS + c4 + 2] = h23;
        *(__nv_bfloat162*)&sAlo[r * SAS + c4]     = l01;
        *(__nv_bfloat162*)&sAlo[r * SAS + c4 + 2] = l23;
    }
    __syncthreads();

    int wm = wid & 1, wn = wid >> 1;
    int m_base = wm * 32, n_base = wn * 32;

    float c[2][4][4];
#pragma unroll
    for (int i = 0; i < 2; i++)
#pragma unroll
        for (int j = 0; j < 4; j++)
#pragma unroll
            for (int q = 0; q < 4; q++) c[i][j][q] = 0.f;

    int a_r = lane & 15, a_c8 = (lane >> 4) << 3;
    int b_r = (((lane >> 4) & 1) << 3) + (lane & 7), b_c8 = ((lane >> 3) & 1) << 3;

#pragma unroll
    for (int ks = 0; ks < 8; ks++) {
        int k0 = ks * 16;
        uint32_t ahi[2][4], alo[2][4];
#pragma unroll
        for (int i = 0; i < 2; i++) {
            uint32_t off = (uint32_t)((m_base + i * 16 + a_r) * SAS + k0 + a_c8) * 2;
            ldm4(ahi[i], uAhi + off);
            ldm4(alo[i], uAlo + off);
        }
#pragma unroll
        for (int jp = 0; jp < 2; jp++) {
            uint32_t off = (uint32_t)((n_base + jp * 16 + b_r) * SAS + k0 + b_c8) * 2;
            uint32_t bh[4], bl[4];
            ldm4(bh, uBhi + off);
            ldm4(bl, uBlo + off);
#pragma unroll
            for (int i = 0; i < 2; i++) {
                mma16816(c[i][2 * jp],     ahi[i], bh[0], bh[1]);
                mma16816(c[i][2 * jp],     alo[i], bh[0], bh[1]);
                mma16816(c[i][2 * jp],     ahi[i], bl[0], bl[1]);
                mma16816(c[i][2 * jp + 1], ahi[i], bh[2], bh[3]);
                mma16816(c[i][2 * jp + 1], alo[i], bh[2], bh[3]);
                mma16816(c[i][2 * jp + 1], ahi[i], bl[2], bl[3]);
            }
        }
    }

    int qr = lane >> 2, qc = (lane & 3) * 2;
#pragma unroll
    for (int i = 0; i < 2; i++) {
#pragma unroll
        for (int j = 0; j < 4; j++) {
            int r0g = row0 + m_base + i * 16 + qr;
            int nn0 = n_base + j * 8 + qc;
            float2 bb = __ldg((const float2*)&bias[nn0]);
            if (r0g < n) {
                float2 o = make_float2(c[i][j][0] + bb.x, c[i][j][1] + bb.y);
                *(float2*)&out[(size_t)r0g * F + nn0] = o;
            }
            if (r0g + 8 < n) {
                float2 o = make_float2(c[i][j][2] + bb.x, c[i][j][3] + bb.y);
                *(float2*)&out[(size_t)(r0g + 8) * F + nn0] = o;
            }
        }
    }
}

// single GEMM (embedding)
__global__ void __launch_bounds__(256, 2) hmma_gemm(
        const float* __restrict__ A,
        const __nv_bfloat16* __restrict__ Whi, const __nv_bfloat16* __restrict__ Wlo,
        const float* __restrict__ bias, float* __restrict__ out, int n) {
    extern __shared__ __align__(16) char smem[];
    gemm_body(A, Whi, Wlo, bias, out, n, smem);
}

// dual GEMM: blockIdx.y selects (Wl -> xl) or (Wr -> xr); one packed launch
__global__ void __launch_bounds__(256, 2) hmma_gemm_dual(
        const float* __restrict__ A,
        const __nv_bfloat16* __restrict__ Whi_l, const __nv_bfloat16* __restrict__ Wlo_l,
        const float* __restrict__ bias_l, float* __restrict__ out_l,
        const __nv_bfloat16* __restrict__ Whi_r, const __nv_bfloat16* __restrict__ Wlo_r,
        const float* __restrict__ bias_r, float* __restrict__ out_r, int n) {
    extern __shared__ __align__(16) char smem[];
    if (blockIdx.y == 0)
        gemm_body(A, Whi_l, Wlo_l, bias_l, out_l, n, smem);
    else
        gemm_body(A, Whi_r, Wlo_r, bias_r, out_r, n, smem);
}

// ---------------- fused gather: softmax-attention aggregate + epilogue --------
__device__ __forceinline__ float lrelu(float v) {
    return (v > 0.f) ? v : 0.2f * v;
}

__device__ __forceinline__ float edge_partial(const float4& xl4, const float4& xr4,
                                              const float4& attv) {
    return lrelu(xl4.x + xr4.x) * attv.x
         + lrelu(xl4.y + xr4.y) * attv.y
         + lrelu(xl4.z + xr4.z) * attv.z
         + lrelu(xl4.w + xr4.w) * attv.w;
}

__global__ void __launch_bounds__(256) gat_gather(
        const float* __restrict__ att, const float* __restrict__ conv_b,
        const float* __restrict__ ln_g, const float* __restrict__ ln_b) {
    int node = (blockIdx.x * blockDim.x + threadIdx.x) >> 5;
    int lane = threadIdx.x & 31;
    if (node >= NN) return;
    int beg = g_rowptr[node];
    int end = g_rowptr[node + 1];

    float4 xr4 = *(const float4*)&g_xr[(size_t)node * F + lane * 4];
    float4 attv = __ldg((const float4*)&att[lane * 4]);

    float d = 0.f;
    float4 s = make_float4(0.f, 0.f, 0.f, 0.f);

    int e = beg;
    for (; e + 4 <= end; e += 4) {
        int si[4];
#pragma unroll
        for (int u = 0; u < 4; u++) si[u] = g_csrsrc[e + u];
        float4 a[4];
#pragma unroll
        for (int u = 0; u < 4; u++)
            a[u] = __ldg((const float4*)&g_xl[(size_t)si[u] * F + lane * 4]);

        float p[4];
#pragma unroll
        for (int u = 0; u < 4; u++) p[u] = edge_partial(a[u], xr4, attv);

#pragma unroll
        for (int off = 1; off <= 4; off <<= 1) {
#pragma unroll
            for (int u = 0; u < 4; u++)
                p[u] += __shfl_xor_sync(0xffffffffu, p[u], off);
        }

#pragma unroll
        for (int u = 0; u < 4; u++) {
            float w = __expf(p[u]);
            d += w;
            s.x += w * a[u].x;
            s.y += w * a[u].y;
            s.z += w * a[u].z;
            s.w += w * a[u].w;
        }
    }
    for (; e < end; e++) {
        int s0 = g_csrsrc[e];
        float4 a0 = __ldg((const float4*)&g_xl[(size_t)s0 * F + lane * 4]);
        float p = edge_partial(a0, xr4, attv);
        p += __shfl_xor_sync(0xffffffffu, p, 1);
        p += __shfl_xor_sync(0xffffffffu, p, 2);
        p += __shfl_xor_sync(0xffffffffu, p, 4);
        float w = __expf(p);
        d += w;
        s.x += w * a0.x;
        s.y += w * a0.y;
        s.z += w * a0.z;
        s.w += w * a0.w;
    }

    float invd = 1.0f / (d + 1e-16f);
    float4 cb = __ldg((const float4*)&conv_b[lane * 4]);
    float4 o;
    o.x = s.x * invd + cb.x;
    o.y = s.y * invd + cb.y;
    o.z = s.z * invd + cb.z;
    o.w = s.w * invd + cb.w;
    o.x = (o.x > 0.f) ? o.x : (__expf(o.x) - 1.f);
    o.y = (o.y > 0.f) ? o.y : (__expf(o.y) - 1.f);
    o.z = (o.z > 0.f) ? o.z : (__expf(o.z) - 1.f);
    o.w = (o.w > 0.f) ? o.w : (__expf(o.w) - 1.f);
    float4 res = *(const float4*)&g_h[(size_t)node * F + lane * 4];
    o.x += res.x; o.y += res.y; o.z += res.z; o.w += res.w;

    float sum = o.x + o.y + o.z + o.w;
#pragma unroll
    for (int off = 16; off; off >>= 1) sum += __shfl_xor_sync(0xffffffffu, sum, off);
    float mu = sum * (1.f / 128.f);
    float dx0 = o.x - mu, dx1 = o.y - mu, dx2 = o.z - mu, dx3 = o.w - mu;
    float sq = dx0 * dx0 + dx1 * dx1 + dx2 * dx2 + dx3 * dx3;
#pragma unroll
    for (int off = 16; off; off >>= 1) sq += __shfl_xor_sync(0xffffffffu, sq, off);
    float rstd = rsqrtf(sq * (1.f / 128.f) + 1e-5f);

    float4 lg = __ldg((const float4*)&ln_g[lane * 4]);
    float4 lb = __ldg((const float4*)&ln_b[lane * 4]);
    float4 w;
    w.x = dx0 * rstd * lg.x + lb.x;
    w.y = dx1 * rstd * lg.y + lb.y;
    w.z = dx2 * rstd * lg.z + lb.z;
    w.w = dx3 * rstd * lg.w + lb.w;
    *(float4*)&g_h[(size_t)node * F + lane * 4] = w;
}

// ---------------- pooling ----------------
__global__ void pool_zero() {
    int i = blockIdx.x * blockDim.x + threadIdx.x;
    if (i < NG * F) g_pool[i] = 0.f;
    if (i < NG) g_cnt[i] = 0.f;
}

__global__ void pool_accum() {
    int node = (blockIdx.x * blockDim.x + threadIdx.x) >> 5;
    int lane = threadIdx.x & 31;
    if (node >= NN) return;
    int g = g_batch32[node];
#pragma unroll
    for (int h = 0; h < HEADS; h++)
        atomicAdd(&g_pool[g * F + h * HD + lane],
                  g_h[(size_t)node * F + h * HD + lane]);
    if (lane == 0) atomicAdd(&g_cnt[g], 1.0f);
}

__global__ void pool_final(float* __restrict__ out) {
    int i = blockIdx.x * blockDim.x + threadIdx.x;
    if (i >= NG * F) return;
    out[i] = g_pool[i] / fmaxf(g_cnt[i >> 7], 1.0f);
}

// ---------------- launch ----------------
extern "C" void kernel_launch(void* const* d_in, const int* in_sizes, int n_in,
                              void* d_out, int out_size) {
    const float* x        = (const float*)d_in[0];
    const void*  ei_raw   = d_in[1];
    const void*  batch_raw= d_in[2];
    const float* emb_W    = (const float*)d_in[3];
    const float* emb_b    = (const float*)d_in[4];
    const float* lin_l_W  = (const float*)d_in[5];
    const float* lin_l_b  = (const float*)d_in[6];
    const float* lin_r_W  = (const float*)d_in[7];
    const float* lin_r_b  = (const float*)d_in[8];
    const float* att      = (const float*)d_in[9];
    const float* conv_b   = (const float*)d_in[10];
    const float* ln_g     = (const float*)d_in[11];
    const float* ln_b     = (const float*)d_in[12];
    float* out = (float*)d_out;

    float *p_h, *p_xl, *p_xr;
    int *p_batch;
    __nv_bfloat16 *p_Whi, *p_Wlo;
    cudaGetSymbolAddress((void**)&p_h, g_h);
    cudaGetSymbolAddress((void**)&p_xl, g_xl);
    cudaGetSymbolAddress((void**)&p_xr, g_xr);
    cudaGetSymbolAddress((void**)&p_batch, g_batch32);
    cudaGetSymbolAddress((void**)&p_Whi, g_Whi);
    cudaGetSymbolAddress((void**)&p_Wlo, g_Wlo);

    cudaFuncSetAttribute(hmma_gemm, cudaFuncAttributeMaxDynamicSharedMemorySize, SMEMSZ);
    cudaFuncSetAttribute(hmma_gemm_dual, cudaFuncAttributeMaxDynamicSharedMemorySize, SMEMSZ);

    // one-time side streams + events (host-side resources; no device memory)
    static cudaStream_t s2 = nullptr, s3 = nullptr;
    static cudaEvent_t evFork = nullptr, evSide = nullptr, evW = nullptr;
    if (!s2) {
        cudaStreamCreateWithFlags(&s2, cudaStreamNonBlocking);
        cudaStreamCreateWithFlags(&s3, cudaStreamNonBlocking);
        cudaEventCreateWithFlags(&evFork, cudaEventDisableTiming);
        cudaEventCreateWithFlags(&evSide, cudaEventDisableTiming);
        cudaEventCreateWithFlags(&evW, cudaEventDisableTiming);
    }

    const int ET_GRID = (NE + 255) / 256;
    const int NW_GRID = (NN + 7) / 8;

    // fork immediately: s2 does sniff + CSR build; s3 does layer-weight split
    cudaEventRecord(evFork, 0);
    cudaStreamWaitEvent(s2, evFork, 0);
    cudaStreamWaitEvent(s3, evFork, 0);

    // side branch (s2): sniff + CSR build + batch convert + pool zero
    sniff_dtype<<<1, 1024, 0, s2>>>(ei_raw);
    csr_count_zero<<<(NN + 255) / 256, 256, 0, s2>>>();
    pool_zero<<<(NG * F + 255) / 256, 256, 0, s2>>>();
    convert_count<<<ET_GRID, 256, 0, s2>>>(ei_raw);
    convert_idx<<<(NN + 255) / 256, 256, 0, s2>>>(batch_raw, p_batch, NN);
    csr_scan<<<1, 1024, 0, s2>>>();
    csr_fill<<<ET_GRID, 256, 0, s2>>>();
    cudaEventRecord(evSide, s2);

    // side branch (s3): layer weight split, concurrent with emb GEMM
    split_W_rest<<<(6 * 16384 + 255) / 256, 256, 0, s3>>>(lin_l_W, lin_r_W);
    cudaEventRecord(evW, s3);

    // main branch: emb weight split + embedding GEMM
    split_W_emb<<<(16384 + 255) / 256, 256>>>(emb_W);
    hmma_gemm<<<TILES64, 256, SMEMSZ>>>(x, p_Whi, p_Wlo, emb_b, p_h, NN);

    // layer weights must be ready before the first dual GEMM
    cudaStreamWaitEvent(0, evW, 0);

    for (int l = 0; l < 3; l++) {
        hmma_gemm_dual<<<dim3(TILES64, 2), 256, SMEMSZ>>>(
            p_h,
            p_Whi + (size_t)(1 + l) * 16384, p_Wlo + (size_t)(1 + l) * 16384,
            lin_l_b + (size_t)l * F, p_xl,
            p_Whi + (size_t)(4 + l) * 16384, p_Wlo + (size_t)(4 + l) * 16384,
            lin_r_b + (size_t)l * F, p_xr, NN);
        if (l == 0) {
            // CSR only needed by the gather — join here so the first dual-GEMM
            // runs concurrently with the tail of the CSR build on s2
            cudaStreamWaitEvent(0, evSide, 0);
        }
        gat_gather<<<NW_GRID, 256>>>(att + (size_t)l * F,
                                     conv_b + (size_t)l * F,
                                     ln_g + (size_t)l * F,
                                     ln_b + (size_t)l * F);
    }

    pool_accum<<<NW_GRID, 256>>>();
    pool_final<<<(NG * F + 255) / 256, 256>>>(out);
}